// round 5
// baseline (speedup 1.0000x reference)
#include <cuda_runtime.h>
#include <cuda_fp16.h>
#include <mma.h>
#include <cstdint>
#include <cstddef>

using namespace nvcuda;

#define NN   16384
#define DF   256
#define KCAT 512

// ---------------- device-global scratch ----------------
__device__ int8_t g_ftT8[(size_t)DF * NN];   // features^T int8 [256][16384]
__device__ __half g_cat[(size_t)NN * KCAT];  // [features | neigh] fp16 [16384][512]
__device__ __half g_w[(size_t)DF * KCAT];    // W fp16 [256][512]
__device__ unsigned g_fmax_bits;             // max|features| as float bits

// ---------------- smem layouts ----------------
constexpr int OFF_B    = 20480;
constexpr int OFF_SROW = 61440;
constexpr int SMEM_BYTES = 61952;
constexpr int AST8 = 80;  // int8 row stride (bytes)
constexpr int AST  = 40;  // fp16 row stride (halves)
constexpr int SST  = 68;  // epilogue stage row stride (32-bit words)

__device__ __forceinline__ uint32_t smem_u32(const void* p) {
    uint32_t a;
    asm("{ .reg .u64 t; cvta.to.shared.u64 t, %1; cvt.u32.u64 %0, t; }" : "=r"(a) : "l"(p));
    return a;
}
__device__ __forceinline__ void cpa16(uint32_t saddr, const void* g) {
    asm volatile("cp.async.cg.shared.global [%0], [%1], 16;" :: "r"(saddr), "l"(g));
}
__device__ __forceinline__ void cpa_commit() { asm volatile("cp.async.commit_group;" ::: "memory"); }
__device__ __forceinline__ void cpa_wait0()  { asm volatile("cp.async.wait_group 0;" ::: "memory"); }

// pack 4 floats (pre-scaled) -> bytes LSB..MSB = sat8(v.x),sat8(v.y),sat8(v.z),sat8(v.w)
// cvt.pack.sat.s8.s32.b32 d,a,b,c: d[7:0]=sat(b), d[15:8]=sat(a), d[31:16]=c[15:0]
__device__ __forceinline__ int quant4(float4 v, float s) {
    int i0 = __float2int_rn(v.x * s), i1 = __float2int_rn(v.y * s);
    int i2 = __float2int_rn(v.z * s), i3 = __float2int_rn(v.w * s);
    int t, r;
    asm("cvt.pack.sat.s8.s32.b32 %0, %1, %2, 0;"  : "=r"(t) : "r"(i3), "r"(i2));  // low={i2,i3}
    asm("cvt.pack.sat.s8.s32.b32 %0, %1, %2, %3;" : "=r"(r) : "r"(i1), "r"(i0), "r"(t)); // i0,i1,i2,i3
    return r;
}

// ---------------- prep chain ----------------
__global__ void k_reset() { g_fmax_bits = 0u; }

__global__ void __launch_bounds__(256) k_scan(const float* __restrict__ f) {
    __shared__ float red[256];
    float m = 0.f;
    int stride = gridDim.x * 256;
    for (int i = blockIdx.x * 256 + threadIdx.x; i < NN * DF / 4; i += stride) {
        float4 v = ((const float4*)f)[i];
        m = fmaxf(m, fmaxf(fmaxf(fabsf(v.x), fabsf(v.y)), fmaxf(fabsf(v.z), fabsf(v.w))));
    }
    red[threadIdx.x] = m;
    __syncthreads();
    for (int s = 128; s > 0; s >>= 1) {
        if (threadIdx.x < s) red[threadIdx.x] = fmaxf(red[threadIdx.x], red[threadIdx.x + s]);
        __syncthreads();
    }
    if (threadIdx.x == 0) atomicMax(&g_fmax_bits, __float_as_uint(red[0]));
}

// features -> g_ftT8 (transposed int8) and g_cat[:, :256] (fp16)
__global__ void __launch_bounds__(256) k_prep(const float* __restrict__ f) {
    __shared__ float t[32][33];
    float sf = 127.0f / __uint_as_float(g_fmax_bits);
    int n0 = blockIdx.x * 32, d0 = blockIdx.y * 32;
    int tx = threadIdx.x, ty = threadIdx.y;
    #pragma unroll
    for (int i = ty; i < 32; i += 8) {
        float v = f[(size_t)(n0 + i) * DF + d0 + tx];
        t[i][tx] = v;
        g_cat[(size_t)(n0 + i) * KCAT + d0 + tx] = __float2half(v);
    }
    __syncthreads();
    #pragma unroll
    for (int i = ty; i < 32; i += 8) {
        int q = __float2int_rn(t[tx][i] * sf);
        int r;
        asm("cvt.pack.sat.s8.s32.b32 %0, %1, %1, 0;" : "=r"(r) : "r"(q));
        g_ftT8[(size_t)(d0 + i) * NN + n0 + tx] = (int8_t)(r & 0xFF);
    }
}

__global__ void __launch_bounds__(256) k_wconv(const float* __restrict__ W) {
    int i = blockIdx.x * 256 + threadIdx.x;
    if (i < DF * KCAT) g_w[i] = __float2half(W[i]);
}

// ================= k_main: neigh = (adj @ F)/(rowsum+1), int8 IMMA, BK=64 =================
__global__ void __launch_bounds__(256, 1) k_main(const float* __restrict__ adj) {
    extern __shared__ char sm[];
    int8_t* Abuf = (int8_t*)sm;             // [2][128][80]
    int8_t* Bbuf = (int8_t*)(sm + OFF_B);   // [2][256][80]
    float*  srow = (float*)(sm + OFF_SROW); // [128]
    int*    istage = (int*)sm;              // [128][68] epilogue reuse

    const int tid = threadIdx.x;
    const int lane = tid & 31;
    const int wid = tid >> 5;
    const int wm = wid >> 2, wn = wid & 3;  // 2x4 warps, 64x64 tiles
    const int m0 = blockIdx.x * 128;
    const uint32_t b_u32 = smem_u32(Bbuf);

    wmma::fragment<wmma::accumulator, 16, 16, 16, int> acc[4][4];
    #pragma unroll
    for (int mi = 0; mi < 4; mi++)
        #pragma unroll
        for (int ni = 0; ni < 4; ni++)
            wmma::fill_fragment(acc[mi][ni], 0);

    float rowacc[8] = {0.f};
    float4 va[8];

    auto ldgA = [&](int it) {
        int k0 = it * 64;
        #pragma unroll
        for (int j = 0; j < 8; j++) {
            int idx = tid + j * 256;
            int row = idx >> 4, c4 = idx & 15;  // 16 float4 per 64-col row
            va[j] = *(const float4*)(adj + (size_t)(m0 + row) * NN + k0 + c4 * 4);
        }
    };
    auto stsA = [&](int buf) {
        int8_t* At = Abuf + buf * 128 * AST8;
        #pragma unroll
        for (int j = 0; j < 8; j++) {
            int idx = tid + j * 256;
            int row = idx >> 4, c4 = idx & 15;
            float4 v = va[j];
            rowacc[j] += (v.x + v.y) + (v.z + v.w);
            *(int*)(At + row * AST8 + c4 * 4) = quant4(v, 127.0f);
        }
    };
    auto cpaB = [&](int buf, int it) {
        int k0 = it * 64;
        uint32_t b0 = b_u32 + buf * 256 * AST8;
        #pragma unroll
        for (int j = 0; j < 4; j++) {
            int idx = tid + j * 256;
            int row = idx >> 2, c16 = idx & 3;  // 4 x 16B per 64-col row
            cpa16(b0 + row * AST8 + c16 * 16, g_ftT8 + (size_t)row * NN + k0 + c16 * 16);
        }
    };

    ldgA(0);
    cpaB(0, 0);
    cpa_commit();

    constexpr int NK = NN / 64;  // 256
    #pragma unroll 1
    for (int it = 0; it < NK; ++it) {
        int cur = it & 1;
        stsA(cur);
        if (it + 1 < NK) ldgA(it + 1);
        cpa_wait0();
        __syncthreads();
        if (it + 1 < NK) { cpaB(cur ^ 1, it + 1); cpa_commit(); }

        const int8_t* At = Abuf + cur * 128 * AST8;
        const int8_t* Bt = Bbuf + cur * 256 * AST8;
        #pragma unroll
        for (int ks = 0; ks < 4; ++ks) {
            wmma::fragment<wmma::matrix_a, 16, 16, 16, signed char, wmma::row_major> af[4];
            #pragma unroll
            for (int mi = 0; mi < 4; mi++)
                wmma::load_matrix_sync(af[mi], (const signed char*)(At + (wm * 64 + mi * 16) * AST8 + ks * 16), AST8);
            #pragma unroll
            for (int ni = 0; ni < 4; ni++) {
                wmma::fragment<wmma::matrix_b, 16, 16, 16, signed char, wmma::col_major> bf;
                wmma::load_matrix_sync(bf, (const signed char*)(Bt + (wn * 64 + ni * 16) * AST8 + ks * 16), AST8);
                #pragma unroll
                for (int mi = 0; mi < 4; mi++)
                    wmma::mma_sync(acc[mi][ni], af[mi], bf, acc[mi][ni]);
            }
        }
    }

    // rowsum -> 1/(deg+1); 16 lanes per row
    #pragma unroll
    for (int j = 0; j < 8; j++) {
        float s = rowacc[j];
        s += __shfl_xor_sync(0xFFFFFFFFu, s, 1);
        s += __shfl_xor_sync(0xFFFFFFFFu, s, 2);
        s += __shfl_xor_sync(0xFFFFFFFFu, s, 4);
        s += __shfl_xor_sync(0xFFFFFFFFu, s, 8);
        int row = (tid + j * 256) >> 4;
        if ((lane & 15) == 0) srow[row] = 1.0f / (s + 1.0f);
    }
    __syncthreads();  // all MMA done; stage may overwrite A/B smem

    float fmax = __uint_as_float(g_fmax_bits);
    float dq = fmax / (127.0f * 127.0f);

    #pragma unroll 1
    for (int p = 0; p < 4; p++) {
        if (wn == p) {
            #pragma unroll
            for (int mi = 0; mi < 4; mi++)
                #pragma unroll
                for (int ni = 0; ni < 4; ni++)
                    wmma::store_matrix_sync(istage + (wm * 64 + mi * 16) * SST + ni * 16,
                                            acc[mi][ni], SST, wmma::mem_row_major);
        }
        __syncthreads();
        #pragma unroll
        for (int j = 0; j < 32; j++) {
            int idx = tid + j * 256;
            int r = idx >> 6, c = idx & 63;
            float v = (float)istage[r * SST + c] * dq * srow[r];
            g_cat[(size_t)(m0 + r) * KCAT + 256 + p * 64 + c] = __float2half(v);
        }
        __syncthreads();
    }
}

// ================= k_out: out = [F|neigh] @ W^T (fp16, K=512) =================
__global__ void __launch_bounds__(256, 1) k_out(float* __restrict__ out) {
    extern __shared__ char sm[];
    __half* Abuf = (__half*)sm;
    __half* Bbuf = (__half*)(sm + OFF_B);
    float*  stage = (float*)sm;

    const int tid = threadIdx.x;
    const int wid = tid >> 5;
    const int wm = wid >> 2, wn = wid & 3;
    const int m0 = blockIdx.x * 128;
    const uint32_t a_u32 = smem_u32(Abuf);
    const uint32_t b_u32 = smem_u32(Bbuf);

    wmma::fragment<wmma::accumulator, 16, 16, 16, float> acc[4][4];
    #pragma unroll
    for (int mi = 0; mi < 4; mi++)
        #pragma unroll
        for (int ni = 0; ni < 4; ni++)
            wmma::fill_fragment(acc[mi][ni], 0.0f);

    auto loadTile = [&](int buf, int it) {
        int k0 = it * 32;
        uint32_t a0 = a_u32 + buf * 128 * AST * 2;
        uint32_t b0 = b_u32 + buf * 256 * AST * 2;
        #pragma unroll
        for (int j = 0; j < 2; j++) {
            int idx = tid + j * 256;
            int row = idx >> 2, c8 = idx & 3;
            cpa16(a0 + (row * AST + c8 * 8) * 2, g_cat + (size_t)(m0 + row) * KCAT + k0 + c8 * 8);
        }
        #pragma unroll
        for (int j = 0; j < 4; j++) {
            int idx = tid + j * 256;
            int row = idx >> 2, c8 = idx & 3;
            cpa16(b0 + (row * AST + c8 * 8) * 2, g_w + (size_t)row * KCAT + k0 + c8 * 8);
        }
    };

    loadTile(0, 0);
    cpa_commit();

    constexpr int NK = KCAT / 32;  // 16
    #pragma unroll 1
    for (int it = 0; it < NK; ++it) {
        int cur = it & 1;
        cpa_wait0();
        __syncthreads();
        if (it + 1 < NK) { loadTile(cur ^ 1, it + 1); cpa_commit(); }

        const __half* At = Abuf + cur * 128 * AST;
        const __half* Bt = Bbuf + cur * 256 * AST;
        #pragma unroll
        for (int ks = 0; ks < 2; ++ks) {
            wmma::fragment<wmma::matrix_a, 16, 16, 16, __half, wmma::row_major> af[4];
            #pragma unroll
            for (int mi = 0; mi < 4; mi++)
                wmma::load_matrix_sync(af[mi], At + (wm * 64 + mi * 16) * AST + ks * 16, AST);
            #pragma unroll
            for (int ni = 0; ni < 4; ni++) {
                wmma::fragment<wmma::matrix_b, 16, 16, 16, __half, wmma::col_major> bf;
                wmma::load_matrix_sync(bf, Bt + (wn * 64 + ni * 16) * AST + ks * 16, AST);
                #pragma unroll
                for (int mi = 0; mi < 4; mi++)
                    wmma::mma_sync(acc[mi][ni], af[mi], bf, acc[mi][ni]);
            }
        }
        __syncthreads();
    }

    #pragma unroll 1
    for (int p = 0; p < 4; p++) {
        if (wn == p) {
            #pragma unroll
            for (int mi = 0; mi < 4; mi++)
                #pragma unroll
                for (int ni = 0; ni < 4; ni++)
                    wmma::store_matrix_sync(stage + (wm * 64 + mi * 16) * SST + ni * 16,
                                            acc[mi][ni], SST, wmma::mem_row_major);
        }
        __syncthreads();
        #pragma unroll
        for (int j = 0; j < 32; j++) {
            int idx = tid + j * 256;
            int r = idx >> 6, c = idx & 63;
            out[(size_t)(m0 + r) * DF + p * 64 + c] = stage[r * SST + c];
        }
        __syncthreads();
    }
}

// ---------------- launch ----------------
extern "C" void kernel_launch(void* const* d_in, const int* in_sizes, int n_in,
                              void* d_out, int out_size) {
    const float* features = nullptr;
    const float* adj = nullptr;
    const float* W = nullptr;
    for (int i = 0; i < n_in; i++) {
        if (in_sizes[i] == NN * NN) adj = (const float*)d_in[i];
        else if (in_sizes[i] == NN * DF) features = (const float*)d_in[i];
        else if (in_sizes[i] == DF * KCAT) W = (const float*)d_in[i];
    }
    float* out = (float*)d_out;

    cudaFuncSetAttribute(k_main, cudaFuncAttributeMaxDynamicSharedMemorySize, SMEM_BYTES);
    cudaFuncSetAttribute(k_out,  cudaFuncAttributeMaxDynamicSharedMemorySize, SMEM_BYTES);

    k_reset<<<1, 1>>>();
    k_scan<<<512, 256>>>(features);
    k_prep<<<dim3(NN / 32, DF / 32), dim3(32, 8)>>>(features);
    k_wconv<<<(DF * KCAT + 255) / 256, 256>>>(W);
    k_main<<<NN / 128, 256, SMEM_BYTES>>>(adj);
    k_out<<<NN / 128, 256, SMEM_BYTES>>>(out);
}

// round 6
// speedup vs baseline: 4.4538x; 4.4538x over previous
#include <cuda_runtime.h>
#include <cuda_fp16.h>
#include <mma.h>
#include <cstdint>
#include <cstddef>

using namespace nvcuda;

#define NN   16384
#define DF   256
#define KCAT 512

// ---------------- device-global scratch ----------------
__device__ __half g_ftT[(size_t)DF * NN];    // features^T fp16 [256][16384]
__device__ __half g_cat[(size_t)NN * KCAT];  // [features | neigh] fp16 [16384][512]
__device__ __half g_w[(size_t)DF * KCAT];    // W fp16 [256][512]

// ---------------- smem layouts ----------------
// k_main (fp16, BK=64): A [2][128][72]h = 36864 B @0, B [2][256][72]h = 73728 B @36864,
//                       srow 128 f @110592;  epilogue stage reuses A region (half [128][72])
// k_out  (fp16, BK=32): A [2][128][40]h @0, B [2][256][40]h @20480, stage f32 [128][68] reuse
constexpr int ASTM = 72;      // k_main smem row stride (halves) = 144 B
constexpr int OFF_BM = 36864;
constexpr int OFF_SROW = 110592;
constexpr int SMEM_MAIN = 111104;

constexpr int AST  = 40;      // k_out row stride (halves)
constexpr int OFF_B = 20480;
constexpr int SST  = 68;      // k_out f32 stage stride
constexpr int SMEM_OUT = 61952;

__device__ __forceinline__ uint32_t smem_u32(const void* p) {
    uint32_t a;
    asm("{ .reg .u64 t; cvta.to.shared.u64 t, %1; cvt.u32.u64 %0, t; }" : "=r"(a) : "l"(p));
    return a;
}
__device__ __forceinline__ void cpa16(uint32_t saddr, const void* g) {
    asm volatile("cp.async.cg.shared.global [%0], [%1], 16;" :: "r"(saddr), "l"(g));
}
__device__ __forceinline__ void cpa_commit() { asm volatile("cp.async.commit_group;" ::: "memory"); }
__device__ __forceinline__ void cpa_wait0()  { asm volatile("cp.async.wait_group 0;" ::: "memory"); }

// ---------------- prep: features -> g_ftT (transpose fp16) + g_cat[:, :256] ----------------
__global__ void __launch_bounds__(256) k_prep(const float* __restrict__ f) {
    __shared__ float t[32][33];
    int n0 = blockIdx.x * 32, d0 = blockIdx.y * 32;
    int tx = threadIdx.x, ty = threadIdx.y;
    #pragma unroll
    for (int i = ty; i < 32; i += 8) {
        float v = f[(size_t)(n0 + i) * DF + d0 + tx];
        t[i][tx] = v;
        g_cat[(size_t)(n0 + i) * KCAT + d0 + tx] = __float2half(v);
    }
    __syncthreads();
    #pragma unroll
    for (int i = ty; i < 32; i += 8)
        g_ftT[(size_t)(d0 + i) * NN + n0 + tx] = __float2half(t[tx][i]);
}

// W conversion split in two so k_main lands on profiler capture slot (launch idx 3)
__global__ void __launch_bounds__(256) k_wconv(const float* __restrict__ W, int base) {
    int i = base + blockIdx.x * 256 + threadIdx.x;
    g_w[i] = __float2half(W[i]);
}

// ================= k_main: neigh = (adj @ F)/(rowsum+1), fp16 HMMA, half accum, BK=64 =================
__global__ void __launch_bounds__(256, 1) k_main(const float* __restrict__ adj) {
    extern __shared__ char sm[];
    __half* Abuf = (__half*)sm;                // [2][128][72]
    __half* Bbuf = (__half*)(sm + OFF_BM);     // [2][256][72]
    float*  srow = (float*)(sm + OFF_SROW);    // [128]
    __half* hstage = (__half*)sm;              // epilogue reuse: [128][72] half

    const int tid = threadIdx.x;
    const int lane = tid & 31;
    const int wid = tid >> 5;
    const int wm = wid >> 2, wn = wid & 3;     // 2x4 warps, 64x64 warp tiles
    const int m0 = blockIdx.x * 128;
    const uint32_t b_u32 = smem_u32(Bbuf);

    wmma::fragment<wmma::accumulator, 16, 16, 16, __half> acc[4][4];
    #pragma unroll
    for (int mi = 0; mi < 4; mi++)
        #pragma unroll
        for (int ni = 0; ni < 4; ni++)
            wmma::fill_fragment(acc[mi][ni], __float2half(0.0f));

    float rowacc[8] = {0.f};
    float4 va[8];

    auto ldgA = [&](int it) {
        int k0 = it * 64;
        #pragma unroll
        for (int j = 0; j < 8; j++) {
            int idx = tid + j * 256;
            int row = idx >> 4, c4 = idx & 15;     // 16 float4 per 64-col row
            va[j] = *(const float4*)(adj + (size_t)(m0 + row) * NN + k0 + c4 * 4);
        }
    };
    auto stsA = [&](int buf) {
        __half* At = Abuf + buf * 128 * ASTM;
        #pragma unroll
        for (int j = 0; j < 8; j++) {
            int idx = tid + j * 256;
            int row = idx >> 4, c4 = idx & 15;
            float4 v = va[j];
            rowacc[j] += (v.x + v.y) + (v.z + v.w);
            __half2 h0 = __floats2half2_rn(v.x, v.y);
            __half2 h1 = __floats2half2_rn(v.z, v.w);
            uint2 u;
            u.x = *(uint32_t*)&h0;
            u.y = *(uint32_t*)&h1;
            *(uint2*)(At + row * ASTM + c4 * 4) = u;
        }
    };
    auto cpaB = [&](int buf, int it) {
        int k0 = it * 64;
        uint32_t b0 = b_u32 + buf * 256 * ASTM * 2;
        #pragma unroll
        for (int j = 0; j < 8; j++) {
            int idx = tid + j * 256;
            int row = idx >> 3, c16 = idx & 7;     // 8 x 16B per 64-half row
            cpa16(b0 + (row * ASTM + c16 * 8) * 2, g_ftT + (size_t)row * NN + k0 + c16 * 8);
        }
    };

    ldgA(0);
    cpaB(0, 0);
    cpa_commit();

    constexpr int NK = NN / 64;  // 256
    #pragma unroll 1
    for (int it = 0; it < NK; ++it) {
        int cur = it & 1;
        stsA(cur);
        if (it + 1 < NK) ldgA(it + 1);
        cpa_wait0();
        __syncthreads();
        if (it + 1 < NK) { cpaB(cur ^ 1, it + 1); cpa_commit(); }

        const __half* At = Abuf + cur * 128 * ASTM;
        const __half* Bt = Bbuf + cur * 256 * ASTM;
        #pragma unroll
        for (int ks = 0; ks < 4; ++ks) {
            wmma::fragment<wmma::matrix_a, 16, 16, 16, __half, wmma::row_major> af[4];
            #pragma unroll
            for (int mi = 0; mi < 4; mi++)
                wmma::load_matrix_sync(af[mi], At + (wm * 64 + mi * 16) * ASTM + ks * 16, ASTM);
            #pragma unroll
            for (int ni = 0; ni < 4; ni++) {
                wmma::fragment<wmma::matrix_b, 16, 16, 16, __half, wmma::col_major> bf;
                wmma::load_matrix_sync(bf, Bt + (wn * 64 + ni * 16) * ASTM + ks * 16, ASTM);
                #pragma unroll
                for (int mi = 0; mi < 4; mi++)
                    wmma::mma_sync(acc[mi][ni], af[mi], bf, acc[mi][ni]);
            }
        }
    }

    // exact fp32 rowsum -> 1/(deg+1); 16 lanes share a row
    #pragma unroll
    for (int j = 0; j < 8; j++) {
        float s = rowacc[j];
        s += __shfl_xor_sync(0xFFFFFFFFu, s, 1);
        s += __shfl_xor_sync(0xFFFFFFFFu, s, 2);
        s += __shfl_xor_sync(0xFFFFFFFFu, s, 4);
        s += __shfl_xor_sync(0xFFFFFFFFu, s, 8);
        int row = (tid + j * 256) >> 4;
        if ((lane & 15) == 0) srow[row] = 1.0f / (s + 1.0f);
    }
    __syncthreads();  // all MMA done; stage may overwrite Abuf smem

    // epilogue: 4 passes of 64 cols through half staging
    #pragma unroll 1
    for (int p = 0; p < 4; p++) {
        if (wn == p) {
            #pragma unroll
            for (int mi = 0; mi < 4; mi++)
                #pragma unroll
                for (int ni = 0; ni < 4; ni++)
                    wmma::store_matrix_sync(hstage + (wm * 64 + mi * 16) * ASTM + ni * 16,
                                            acc[mi][ni], ASTM, wmma::mem_row_major);
        }
        __syncthreads();
        #pragma unroll
        for (int j = 0; j < 32; j++) {
            int idx = tid + j * 256;
            int r = idx >> 6, c = idx & 63;
            float v = __half2float(hstage[r * ASTM + c]) * srow[r];
            g_cat[(size_t)(m0 + r) * KCAT + 256 + p * 64 + c] = __float2half(v);
        }
        __syncthreads();
    }
}

// ================= k_out: out = [F|neigh] @ W^T (fp16, fp32 acc, K=512) =================
__global__ void __launch_bounds__(256, 1) k_out(float* __restrict__ out) {
    extern __shared__ char sm[];
    __half* Abuf = (__half*)sm;
    __half* Bbuf = (__half*)(sm + OFF_B);
    float*  stage = (float*)sm;

    const int tid = threadIdx.x;
    const int wid = tid >> 5;
    const int wm = wid >> 2, wn = wid & 3;
    const int m0 = blockIdx.x * 128;
    const uint32_t a_u32 = smem_u32(Abuf);
    const uint32_t b_u32 = smem_u32(Bbuf);

    wmma::fragment<wmma::accumulator, 16, 16, 16, float> acc[4][4];
    #pragma unroll
    for (int mi = 0; mi < 4; mi++)
        #pragma unroll
        for (int ni = 0; ni < 4; ni++)
            wmma::fill_fragment(acc[mi][ni], 0.0f);

    auto loadTile = [&](int buf, int it) {
        int k0 = it * 32;
        uint32_t a0 = a_u32 + buf * 128 * AST * 2;
        uint32_t b0 = b_u32 + buf * 256 * AST * 2;
        #pragma unroll
        for (int j = 0; j < 2; j++) {
            int idx = tid + j * 256;
            int row = idx >> 2, c8 = idx & 3;
            cpa16(a0 + (row * AST + c8 * 8) * 2, g_cat + (size_t)(m0 + row) * KCAT + k0 + c8 * 8);
        }
        #pragma unroll
        for (int j = 0; j < 4; j++) {
            int idx = tid + j * 256;
            int row = idx >> 2, c8 = idx & 3;
            cpa16(b0 + (row * AST + c8 * 8) * 2, g_w + (size_t)row * KCAT + k0 + c8 * 8);
        }
    };

    loadTile(0, 0);
    cpa_commit();

    constexpr int NK = KCAT / 32;  // 16
    #pragma unroll 1
    for (int it = 0; it < NK; ++it) {
        int cur = it & 1;
        cpa_wait0();
        __syncthreads();
        if (it + 1 < NK) { loadTile(cur ^ 1, it + 1); cpa_commit(); }

        const __half* At = Abuf + cur * 128 * AST;
        const __half* Bt = Bbuf + cur * 256 * AST;
        #pragma unroll
        for (int ks = 0; ks < 2; ++ks) {
            wmma::fragment<wmma::matrix_a, 16, 16, 16, __half, wmma::row_major> af[4];
            #pragma unroll
            for (int mi = 0; mi < 4; mi++)
                wmma::load_matrix_sync(af[mi], At + (wm * 64 + mi * 16) * AST + ks * 16, AST);
            #pragma unroll
            for (int ni = 0; ni < 4; ni++) {
                wmma::fragment<wmma::matrix_b, 16, 16, 16, __half, wmma::col_major> bf;
                wmma::load_matrix_sync(bf, Bt + (wn * 64 + ni * 16) * AST + ks * 16, AST);
                #pragma unroll
                for (int mi = 0; mi < 4; mi++)
                    wmma::mma_sync(acc[mi][ni], af[mi], bf, acc[mi][ni]);
            }
        }
        __syncthreads();
    }

    #pragma unroll 1
    for (int p = 0; p < 4; p++) {
        if (wn == p) {
            #pragma unroll
            for (int mi = 0; mi < 4; mi++)
                #pragma unroll
                for (int ni = 0; ni < 4; ni++)
                    wmma::store_matrix_sync(stage + (wm * 64 + mi * 16) * SST + ni * 16,
                                            acc[mi][ni], SST, wmma::mem_row_major);
        }
        __syncthreads();
        #pragma unroll
        for (int j = 0; j < 32; j++) {
            int idx = tid + j * 256;
            int r = idx >> 6, c = idx & 63;
            out[(size_t)(m0 + r) * DF + p * 64 + c] = stage[r * SST + c];
        }
        __syncthreads();
    }
}

// ---------------- launch ----------------
extern "C" void kernel_launch(void* const* d_in, const int* in_sizes, int n_in,
                              void* d_out, int out_size) {
    const float* features = nullptr;
    const float* adj = nullptr;
    const float* W = nullptr;
    for (int i = 0; i < n_in; i++) {
        if (in_sizes[i] == NN * NN) adj = (const float*)d_in[i];
        else if (in_sizes[i] == NN * DF) features = (const float*)d_in[i];
        else if (in_sizes[i] == DF * KCAT) W = (const float*)d_in[i];
    }
    float* out = (float*)d_out;

    cudaFuncSetAttribute(k_main, cudaFuncAttributeMaxDynamicSharedMemorySize, SMEM_MAIN);
    cudaFuncSetAttribute(k_out,  cudaFuncAttributeMaxDynamicSharedMemorySize, SMEM_OUT);

    // launch order puts k_main at 0-based index 3 = ncu capture slot (observed R2/R5)
    k_prep<<<dim3(NN / 32, DF / 32), dim3(32, 8)>>>(features);
    k_wconv<<<(DF * KCAT / 2) / 256, 256>>>(W, 0);
    k_wconv<<<(DF * KCAT / 2) / 256, 256>>>(W, DF * KCAT / 2);
    k_main<<<NN / 128, 256, SMEM_MAIN>>>(adj);
    k_out<<<NN / 128, 256, SMEM_OUT>>>(out);
}

// round 7
// speedup vs baseline: 4.4596x; 1.0013x over previous
#include <cuda_runtime.h>
#include <cuda_fp16.h>
#include <mma.h>
#include <cstdint>
#include <cstddef>

using namespace nvcuda;

#define NN   16384
#define DF   256
#define KCAT 512

// ---------------- device-global scratch ----------------
__device__ __half g_ftT[(size_t)DF * NN];    // features^T fp16 [256][16384]
__device__ __half g_cat[(size_t)NN * KCAT];  // [features | neigh] fp16 [16384][512]
__device__ __half g_w[(size_t)DF * KCAT];    // W fp16 [256][512]

// ---------------- smem layouts ----------------
// k_main: A [2][128][72]h = 36864 B @0 ; B [3][256][72]h = 110592 B @36864 ; srow @147456
constexpr int ASTM = 72;                 // row stride (halves) = 144 B
constexpr int A_STG = 128 * ASTM * 2;    // 18432 B per A stage
constexpr int B_STG = 256 * ASTM * 2;    // 36864 B per B stage
constexpr int OFF_BM = 2 * A_STG;        // 36864
constexpr int OFF_SROW = OFF_BM + 3 * B_STG;  // 147456
constexpr int SMEM_MAIN = OFF_SROW + 512;     // 147968

// k_out: A [2][128][40]h @0, B [2][256][40]h @20480, f32 stage [128][68] reuse
constexpr int AST  = 40;
constexpr int OFF_B = 20480;
constexpr int SST  = 68;
constexpr int SMEM_OUT = 61952;

__device__ __forceinline__ uint32_t smem_u32(const void* p) {
    uint32_t a;
    asm("{ .reg .u64 t; cvta.to.shared.u64 t, %1; cvt.u32.u64 %0, t; }" : "=r"(a) : "l"(p));
    return a;
}
__device__ __forceinline__ void cpa16(uint32_t saddr, const void* g) {
    asm volatile("cp.async.cg.shared.global [%0], [%1], 16;" :: "r"(saddr), "l"(g));
}
__device__ __forceinline__ void cpa_commit() { asm volatile("cp.async.commit_group;" ::: "memory"); }
__device__ __forceinline__ void cpa_wait0()  { asm volatile("cp.async.wait_group 0;" ::: "memory"); }
__device__ __forceinline__ void cpa_wait1()  { asm volatile("cp.async.wait_group 1;" ::: "memory"); }

// ---------------- prep ----------------
__global__ void __launch_bounds__(256) k_prep(const float* __restrict__ f) {
    __shared__ float t[32][33];
    int n0 = blockIdx.x * 32, d0 = blockIdx.y * 32;
    int tx = threadIdx.x, ty = threadIdx.y;
    #pragma unroll
    for (int i = ty; i < 32; i += 8) {
        float v = f[(size_t)(n0 + i) * DF + d0 + tx];
        t[i][tx] = v;
        g_cat[(size_t)(n0 + i) * KCAT + d0 + tx] = __float2half(v);
    }
    __syncthreads();
    #pragma unroll
    for (int i = ty; i < 32; i += 8)
        g_ftT[(size_t)(d0 + i) * NN + n0 + tx] = __float2half(t[tx][i]);
}

__global__ void __launch_bounds__(256) k_wconv(const float* __restrict__ W, int base) {
    int i = base + blockIdx.x * 256 + threadIdx.x;
    g_w[i] = __float2half(W[i]);
}

// ================= k_main: software-pipelined, stores overlapped with MMA =================
__global__ void __launch_bounds__(256, 1) k_main(const float* __restrict__ adj) {
    extern __shared__ char sm[];
    __half* Abuf = (__half*)sm;                // [2][128][72]
    __half* Bbuf = (__half*)(sm + OFF_BM);     // [3][256][72]
    float*  srow = (float*)(sm + OFF_SROW);    // [128]
    __half* hstage = (__half*)sm;              // epilogue reuse

    const int tid = threadIdx.x;
    const int lane = tid & 31;
    const int wid = tid >> 5;
    const int wm = wid >> 2, wn = wid & 3;     // 2x4 warps, 64x64 tiles
    const int m0 = blockIdx.x * 128;
    const uint32_t b_u32 = smem_u32(Bbuf);

    wmma::fragment<wmma::accumulator, 16, 16, 16, __half> acc[4][4];
    #pragma unroll
    for (int mi = 0; mi < 4; mi++)
        #pragma unroll
        for (int ni = 0; ni < 4; ni++)
            wmma::fill_fragment(acc[mi][ni], __float2half(0.0f));

    float rowacc[8] = {0.f};
    float4 va[8];

    auto ldgA = [&](int it) {
        int k0 = it * 64;
        #pragma unroll
        for (int j = 0; j < 8; j++) {
            int idx = tid + j * 256;
            int row = idx >> 4, c4 = idx & 15;
            va[j] = *(const float4*)(adj + (size_t)(m0 + row) * NN + k0 + c4 * 4);
        }
    };
    auto stsA = [&](int buf) {
        __half* At = Abuf + buf * 128 * ASTM;
        #pragma unroll
        for (int j = 0; j < 8; j++) {
            int idx = tid + j * 256;
            int row = idx >> 4, c4 = idx & 15;
            float4 v = va[j];
            rowacc[j] += (v.x + v.y) + (v.z + v.w);
            __half2 h0 = __floats2half2_rn(v.x, v.y);
            __half2 h1 = __floats2half2_rn(v.z, v.w);
            uint2 u;
            u.x = *(uint32_t*)&h0;
            u.y = *(uint32_t*)&h1;
            *(uint2*)(At + row * ASTM + c4 * 4) = u;
        }
    };
    auto cpaB = [&](int buf, int it) {
        int k0 = it * 64;
        uint32_t b0 = b_u32 + buf * B_STG;
        #pragma unroll
        for (int j = 0; j < 8; j++) {
            int idx = tid + j * 256;
            int row = idx >> 3, c16 = idx & 7;
            cpa16(b0 + (row * ASTM + c16 * 8) * 2, g_ftT + (size_t)row * NN + k0 + c16 * 8);
        }
    };

    // ---- prologue ----
    ldgA(0);
    stsA(0);            // A(0) -> buf0 (+rowsum chunk 0)
    ldgA(1);            // va = A(1) data
    cpaB(0, 0); cpa_commit();
    cpaB(1, 1); cpa_commit();

    constexpr int NK = NN / 64;  // 256
    int bs = 0, bs2 = 2;         // it%3, (it+2)%3

    #pragma unroll 1
    for (int it = 0; it < NK; ++it) {
        int cur = it & 1;
        cpa_wait1();       // B(it) arrived (B(it+1) may be in flight)
        __syncthreads();   // A(it) + B(it) visible to all; prior reads of A[cur^1], B[bs2] done

        // --- next-tile feeds: NO barrier between these and the MMAs below ---
        if (it + 1 < NK) stsA(cur ^ 1);      // A(it+1) from va
        if (it + 2 < NK) {
            ldgA(it + 2);                    // refill va
            cpaB(bs2, it + 2);
        }
        cpa_commit();                        // keep group count in lockstep

        const __half* At = Abuf + cur * 128 * ASTM;
        const __half* Bt = Bbuf + bs * 256 * ASTM;
        #pragma unroll
        for (int ks = 0; ks < 4; ++ks) {
            wmma::fragment<wmma::matrix_a, 16, 16, 16, __half, wmma::row_major> af[4];
            #pragma unroll
            for (int mi = 0; mi < 4; mi++)
                wmma::load_matrix_sync(af[mi], At + (wm * 64 + mi * 16) * ASTM + ks * 16, ASTM);
            #pragma unroll
            for (int ni = 0; ni < 4; ni++) {
                wmma::fragment<wmma::matrix_b, 16, 16, 16, __half, wmma::col_major> bf;
                wmma::load_matrix_sync(bf, Bt + (wn * 64 + ni * 16) * ASTM + ks * 16, ASTM);
                #pragma unroll
                for (int mi = 0; mi < 4; mi++)
                    wmma::mma_sync(acc[mi][ni], af[mi], bf, acc[mi][ni]);
            }
        }
        bs = (bs == 2) ? 0 : bs + 1;
        bs2 = (bs2 == 2) ? 0 : bs2 + 1;
    }
    cpa_wait0();  // drain outstanding cp.async before smem reuse

    // exact fp32 rowsum -> 1/(deg+1); 16 lanes share a row
    #pragma unroll
    for (int j = 0; j < 8; j++) {
        float s = rowacc[j];
        s += __shfl_xor_sync(0xFFFFFFFFu, s, 1);
        s += __shfl_xor_sync(0xFFFFFFFFu, s, 2);
        s += __shfl_xor_sync(0xFFFFFFFFu, s, 4);
        s += __shfl_xor_sync(0xFFFFFFFFu, s, 8);
        int row = (tid + j * 256) >> 4;
        if ((lane & 15) == 0) srow[row] = 1.0f / (s + 1.0f);
    }
    __syncthreads();  // all MMA done; stage may overwrite Abuf

    #pragma unroll 1
    for (int p = 0; p < 4; p++) {
        if (wn == p) {
            #pragma unroll
            for (int mi = 0; mi < 4; mi++)
                #pragma unroll
                for (int ni = 0; ni < 4; ni++)
                    wmma::store_matrix_sync(hstage + (wm * 64 + mi * 16) * ASTM + ni * 16,
                                            acc[mi][ni], ASTM, wmma::mem_row_major);
        }
        __syncthreads();
        #pragma unroll
        for (int j = 0; j < 32; j++) {
            int idx = tid + j * 256;
            int r = idx >> 6, c = idx & 63;
            float v = __half2float(hstage[r * ASTM + c]) * srow[r];
            g_cat[(size_t)(m0 + r) * KCAT + 256 + p * 64 + c] = __float2half(v);
        }
        __syncthreads();
    }
}

// ================= k_out: out = [F|neigh] @ W^T (fp16, fp32 acc, K=512) =================
__global__ void __launch_bounds__(256, 1) k_out(float* __restrict__ out) {
    extern __shared__ char sm[];
    __half* Abuf = (__half*)sm;
    __half* Bbuf = (__half*)(sm + OFF_B);
    float*  stage = (float*)sm;

    const int tid = threadIdx.x;
    const int wid = tid >> 5;
    const int wm = wid >> 2, wn = wid & 3;
    const int m0 = blockIdx.x * 128;
    const uint32_t a_u32 = smem_u32(Abuf);
    const uint32_t b_u32 = smem_u32(Bbuf);

    wmma::fragment<wmma::accumulator, 16, 16, 16, float> acc[4][4];
    #pragma unroll
    for (int mi = 0; mi < 4; mi++)
        #pragma unroll
        for (int ni = 0; ni < 4; ni++)
            wmma::fill_fragment(acc[mi][ni], 0.0f);

    auto loadTile = [&](int buf, int it) {
        int k0 = it * 32;
        uint32_t a0 = a_u32 + buf * 128 * AST * 2;
        uint32_t b0 = b_u32 + buf * 256 * AST * 2;
        #pragma unroll
        for (int j = 0; j < 2; j++) {
            int idx = tid + j * 256;
            int row = idx >> 2, c8 = idx & 3;
            cpa16(a0 + (row * AST + c8 * 8) * 2, g_cat + (size_t)(m0 + row) * KCAT + k0 + c8 * 8);
        }
        #pragma unroll
        for (int j = 0; j < 4; j++) {
            int idx = tid + j * 256;
            int row = idx >> 2, c8 = idx & 3;
            cpa16(b0 + (row * AST + c8 * 8) * 2, g_w + (size_t)row * KCAT + k0 + c8 * 8);
        }
    };

    loadTile(0, 0);
    cpa_commit();

    constexpr int NK = KCAT / 32;  // 16
    #pragma unroll 1
    for (int it = 0; it < NK; ++it) {
        int cur = it & 1;
        cpa_wait0();
        __syncthreads();
        if (it + 1 < NK) { loadTile(cur ^ 1, it + 1); cpa_commit(); }

        const __half* At = Abuf + cur * 128 * AST;
        const __half* Bt = Bbuf + cur * 256 * AST;
        #pragma unroll
        for (int ks = 0; ks < 2; ++ks) {
            wmma::fragment<wmma::matrix_a, 16, 16, 16, __half, wmma::row_major> af[4];
            #pragma unroll
            for (int mi = 0; mi < 4; mi++)
                wmma::load_matrix_sync(af[mi], At + (wm * 64 + mi * 16) * AST + ks * 16, AST);
            #pragma unroll
            for (int ni = 0; ni < 4; ni++) {
                wmma::fragment<wmma::matrix_b, 16, 16, 16, __half, wmma::col_major> bf;
                wmma::load_matrix_sync(bf, Bt + (wn * 64 + ni * 16) * AST + ks * 16, AST);
                #pragma unroll
                for (int mi = 0; mi < 4; mi++)
                    wmma::mma_sync(acc[mi][ni], af[mi], bf, acc[mi][ni]);
            }
        }
        __syncthreads();
    }

    #pragma unroll 1
    for (int p = 0; p < 4; p++) {
        if (wn == p) {
            #pragma unroll
            for (int mi = 0; mi < 4; mi++)
                #pragma unroll
                for (int ni = 0; ni < 4; ni++)
                    wmma::store_matrix_sync(stage + (wm * 64 + mi * 16) * SST + ni * 16,
                                            acc[mi][ni], SST, wmma::mem_row_major);
        }
        __syncthreads();
        #pragma unroll
        for (int j = 0; j < 32; j++) {
            int idx = tid + j * 256;
            int r = idx >> 6, c = idx & 63;
            out[(size_t)(m0 + r) * DF + p * 64 + c] = stage[r * SST + c];
        }
        __syncthreads();
    }
}

// ---------------- launch ----------------
extern "C" void kernel_launch(void* const* d_in, const int* in_sizes, int n_in,
                              void* d_out, int out_size) {
    const float* features = nullptr;
    const float* adj = nullptr;
    const float* W = nullptr;
    for (int i = 0; i < n_in; i++) {
        if (in_sizes[i] == NN * NN) adj = (const float*)d_in[i];
        else if (in_sizes[i] == NN * DF) features = (const float*)d_in[i];
        else if (in_sizes[i] == DF * KCAT) W = (const float*)d_in[i];
    }
    float* out = (float*)d_out;

    cudaFuncSetAttribute(k_main, cudaFuncAttributeMaxDynamicSharedMemorySize, SMEM_MAIN);
    cudaFuncSetAttribute(k_out,  cudaFuncAttributeMaxDynamicSharedMemorySize, SMEM_OUT);

    // k_main stays at launch index 3 (ncu capture slot)
    k_prep<<<dim3(NN / 32, DF / 32), dim3(32, 8)>>>(features);
    k_wconv<<<(DF * KCAT / 2) / 256, 256>>>(W, 0);
    k_wconv<<<(DF * KCAT / 2) / 256, 256>>>(W, DF * KCAT / 2);
    k_main<<<NN / 128, 256, SMEM_MAIN>>>(adj);
    k_out<<<NN / 128, 256, SMEM_OUT>>>(out);
}

// round 8
// speedup vs baseline: 4.5505x; 1.0204x over previous
#include <cuda_runtime.h>
#include <cuda_fp16.h>
#include <mma.h>
#include <cstdint>
#include <cstddef>

using namespace nvcuda;

#define NN   16384
#define DF   256
#define KCAT 512

// ---------------- device-global scratch ----------------
__device__ __half g_ftT[(size_t)DF * NN];    // features^T fp16 [256][16384]
__device__ __half g_cat[(size_t)NN * KCAT];  // [features | neigh] fp16 [16384][512]
__device__ __half g_w[(size_t)DF * KCAT];    // W fp16 [256][512]

// ---------------- smem layouts ----------------
// k_main: A [2][128][72]h @0 ; B [3][256][72]h @36864 ; srow @147456
constexpr int ASTM = 72;
constexpr int A_STG = 128 * ASTM * 2;         // 18432
constexpr int B_STG = 256 * ASTM * 2;         // 36864
constexpr int OFF_BM = 2 * A_STG;             // 36864
constexpr int OFF_SROW = OFF_BM + 3 * B_STG;  // 147456
constexpr int SMEM_MAIN = OFF_SROW + 512;

// k_out: A [2][128][40]h @0, B [2][256][40]h @20480, f32 stage [128][68] reuse
constexpr int AST  = 40;
constexpr int OFF_B = 20480;
constexpr int SST  = 68;
constexpr int SMEM_OUT = 61952;

__device__ __forceinline__ uint32_t smem_u32(const void* p) {
    uint32_t a;
    asm("{ .reg .u64 t; cvta.to.shared.u64 t, %1; cvt.u32.u64 %0, t; }" : "=r"(a) : "l"(p));
    return a;
}
__device__ __forceinline__ void cpa16(uint32_t saddr, const void* g) {
    asm volatile("cp.async.cg.shared.global [%0], [%1], 16;" :: "r"(saddr), "l"(g));
}
__device__ __forceinline__ void cpa_commit() { asm volatile("cp.async.commit_group;" ::: "memory"); }
__device__ __forceinline__ void cpa_wait0()  { asm volatile("cp.async.wait_group 0;" ::: "memory"); }
__device__ __forceinline__ void cpa_wait1()  { asm volatile("cp.async.wait_group 1;" ::: "memory"); }

// ---------------- prep ----------------
__global__ void __launch_bounds__(256) k_prep(const float* __restrict__ f) {
    __shared__ float t[32][33];
    int n0 = blockIdx.x * 32, d0 = blockIdx.y * 32;
    int tx = threadIdx.x, ty = threadIdx.y;
    #pragma unroll
    for (int i = ty; i < 32; i += 8) {
        float v = f[(size_t)(n0 + i) * DF + d0 + tx];
        t[i][tx] = v;
        g_cat[(size_t)(n0 + i) * KCAT + d0 + tx] = __float2half(v);
    }
    __syncthreads();
    #pragma unroll
    for (int i = ty; i < 32; i += 8)
        g_ftT[(size_t)(d0 + i) * NN + n0 + tx] = __float2half(t[tx][i]);
}

__global__ void __launch_bounds__(256) k_wconv(const float* __restrict__ W, int base) {
    int i = base + blockIdx.x * 256 + threadIdx.x;
    g_w[i] = __float2half(W[i]);
}

// ================= k_main: 512 threads, 16 warps (4/SMSP), warp tile 32x64 =================
__global__ void __launch_bounds__(512, 1) k_main(const float* __restrict__ adj) {
    extern __shared__ char sm[];
    __half* Abuf = (__half*)sm;                // [2][128][72]
    __half* Bbuf = (__half*)(sm + OFF_BM);     // [3][256][72]
    float*  srow = (float*)(sm + OFF_SROW);    // [128]
    __half* hstage = (__half*)sm;              // epilogue reuse [128][72]

    const int tid = threadIdx.x;
    const int lane = tid & 31;
    const int wid = tid >> 5;
    const int wm = wid >> 2, wn = wid & 3;     // 4x4 warp grid, 32x64 warp tiles
    const int m0 = blockIdx.x * 128;
    const uint32_t b_u32 = smem_u32(Bbuf);

    wmma::fragment<wmma::accumulator, 16, 16, 16, __half> acc[2][4];
    #pragma unroll
    for (int mi = 0; mi < 2; mi++)
        #pragma unroll
        for (int ni = 0; ni < 4; ni++)
            wmma::fill_fragment(acc[mi][ni], __float2half(0.0f));

    float rowacc[4] = {0.f, 0.f, 0.f, 0.f};
    float4 va[4];

    auto ldgA = [&](int it) {
        int k0 = it * 64;
        #pragma unroll
        for (int j = 0; j < 4; j++) {
            int idx = tid + j * 512;
            int row = idx >> 4, c4 = idx & 15;     // 16 float4 per 64-col row
            va[j] = *(const float4*)(adj + (size_t)(m0 + row) * NN + k0 + c4 * 4);
        }
    };
    auto stsA = [&](int buf) {
        __half* At = Abuf + buf * 128 * ASTM;
        #pragma unroll
        for (int j = 0; j < 4; j++) {
            int idx = tid + j * 512;
            int row = idx >> 4, c4 = idx & 15;
            float4 v = va[j];
            rowacc[j] += (v.x + v.y) + (v.z + v.w);
            __half2 h0 = __floats2half2_rn(v.x, v.y);
            __half2 h1 = __floats2half2_rn(v.z, v.w);
            uint2 u;
            u.x = *(uint32_t*)&h0;
            u.y = *(uint32_t*)&h1;
            *(uint2*)(At + row * ASTM + c4 * 4) = u;
        }
    };
    auto cpaB = [&](int buf, int it) {
        int k0 = it * 64;
        uint32_t b0 = b_u32 + buf * B_STG;
        #pragma unroll
        for (int j = 0; j < 4; j++) {
            int idx = tid + j * 512;
            int row = idx >> 3, c16 = idx & 7;     // 8 x 16B per 64-half row
            cpa16(b0 + (row * ASTM + c16 * 8) * 2, g_ftT + (size_t)row * NN + k0 + c16 * 8);
        }
    };

    // ---- prologue ----
    ldgA(0);
    stsA(0);
    ldgA(1);
    cpaB(0, 0); cpa_commit();
    cpaB(1, 1); cpa_commit();

    constexpr int NK = NN / 64;  // 256
    int bs = 0, bs2 = 2;

    #pragma unroll 1
    for (int it = 0; it < NK; ++it) {
        int cur = it & 1;
        cpa_wait1();       // B(it) arrived
        __syncthreads();   // A(it)+B(it) visible; prior reads of A[cur^1], B[bs2] done

        if (it + 1 < NK) stsA(cur ^ 1);
        if (it + 2 < NK) {
            ldgA(it + 2);
            cpaB(bs2, it + 2);
        }
        cpa_commit();

        const __half* At = Abuf + cur * 128 * ASTM;
        const __half* Bt = Bbuf + bs * 256 * ASTM;
        #pragma unroll
        for (int ks = 0; ks < 4; ++ks) {
            wmma::fragment<wmma::matrix_a, 16, 16, 16, __half, wmma::row_major> af[2];
            #pragma unroll
            for (int mi = 0; mi < 2; mi++)
                wmma::load_matrix_sync(af[mi], At + (wm * 32 + mi * 16) * ASTM + ks * 16, ASTM);
            #pragma unroll
            for (int ni = 0; ni < 4; ni++) {
                wmma::fragment<wmma::matrix_b, 16, 16, 16, __half, wmma::col_major> bf;
                wmma::load_matrix_sync(bf, Bt + (wn * 64 + ni * 16) * ASTM + ks * 16, ASTM);
                #pragma unroll
                for (int mi = 0; mi < 2; mi++)
                    wmma::mma_sync(acc[mi][ni], af[mi], bf, acc[mi][ni]);
            }
        }
        bs = (bs == 2) ? 0 : bs + 1;
        bs2 = (bs2 == 2) ? 0 : bs2 + 1;
    }
    cpa_wait0();

    // exact fp32 rowsum -> 1/(deg+1); 16 lanes share a row
    #pragma unroll
    for (int j = 0; j < 4; j++) {
        float s = rowacc[j];
        s += __shfl_xor_sync(0xFFFFFFFFu, s, 1);
        s += __shfl_xor_sync(0xFFFFFFFFu, s, 2);
        s += __shfl_xor_sync(0xFFFFFFFFu, s, 4);
        s += __shfl_xor_sync(0xFFFFFFFFu, s, 8);
        int row = (tid + j * 512) >> 4;
        if ((lane & 15) == 0) srow[row] = 1.0f / (s + 1.0f);
    }
    __syncthreads();  // all MMA done; stage may overwrite Abuf

    // epilogue: 4 passes of 64 cols
    #pragma unroll 1
    for (int p = 0; p < 4; p++) {
        if (wn == p) {
            #pragma unroll
            for (int mi = 0; mi < 2; mi++)
                #pragma unroll
                for (int ni = 0; ni < 4; ni++)
                    wmma::store_matrix_sync(hstage + (wm * 32 + mi * 16) * ASTM + ni * 16,
                                            acc[mi][ni], ASTM, wmma::mem_row_major);
        }
        __syncthreads();
        #pragma unroll
        for (int j = 0; j < 16; j++) {
            int idx = tid + j * 512;
            int r = idx >> 6, c = idx & 63;
            float v = __half2float(hstage[r * ASTM + c]) * srow[r];
            g_cat[(size_t)(m0 + r) * KCAT + 256 + p * 64 + c] = __float2half(v);
        }
        __syncthreads();
    }
}

// ================= k_out: 512 threads, 16 warps, warp tile 32x64, fp32 acc =================
__global__ void __launch_bounds__(512, 1) k_out(float* __restrict__ out) {
    extern __shared__ char sm[];
    __half* Abuf = (__half*)sm;
    __half* Bbuf = (__half*)(sm + OFF_B);
    float*  stage = (float*)sm;

    const int tid = threadIdx.x;
    const int wid = tid >> 5;
    const int wm = wid >> 2, wn = wid & 3;     // 4x4 warps, 32x64 tiles
    const int m0 = blockIdx.x * 128;
    const uint32_t a_u32 = smem_u32(Abuf);
    const uint32_t b_u32 = smem_u32(Bbuf);

    wmma::fragment<wmma::accumulator, 16, 16, 16, float> acc[2][4];
    #pragma unroll
    for (int mi = 0; mi < 2; mi++)
        #pragma unroll
        for (int ni = 0; ni < 4; ni++)
            wmma::fill_fragment(acc[mi][ni], 0.0f);

    auto loadTile = [&](int buf, int it) {
        int k0 = it * 32;
        uint32_t a0 = a_u32 + buf * 128 * AST * 2;
        uint32_t b0 = b_u32 + buf * 256 * AST * 2;
        {   // A: 128 rows x 4 chunks = 512
            int row = tid >> 2, c8 = tid & 3;
            cpa16(a0 + (row * AST + c8 * 8) * 2, g_cat + (size_t)(m0 + row) * KCAT + k0 + c8 * 8);
        }
        #pragma unroll
        for (int j = 0; j < 2; j++) {  // B: 256 rows x 4 chunks = 1024
            int idx = tid + j * 512;
            int row = idx >> 2, c8 = idx & 3;
            cpa16(b0 + (row * AST + c8 * 8) * 2, g_w + (size_t)row * KCAT + k0 + c8 * 8);
        }
    };

    loadTile(0, 0);
    cpa_commit();

    constexpr int NK = KCAT / 32;  // 16
    #pragma unroll 1
    for (int it = 0; it < NK; ++it) {
        int cur = it & 1;
        cpa_wait0();
        __syncthreads();
        if (it + 1 < NK) { loadTile(cur ^ 1, it + 1); cpa_commit(); }

        const __half* At = Abuf + cur * 128 * AST;
        const __half* Bt = Bbuf + cur * 256 * AST;
        #pragma unroll
        for (int ks = 0; ks < 2; ++ks) {
            wmma::fragment<wmma::matrix_a, 16, 16, 16, __half, wmma::row_major> af[2];
            #pragma unroll
            for (int mi = 0; mi < 2; mi++)
                wmma::load_matrix_sync(af[mi], At + (wm * 32 + mi * 16) * AST + ks * 16, AST);
            #pragma unroll
            for (int ni = 0; ni < 4; ni++) {
                wmma::fragment<wmma::matrix_b, 16, 16, 16, __half, wmma::col_major> bf;
                wmma::load_matrix_sync(bf, Bt + (wn * 64 + ni * 16) * AST + ks * 16, AST);
                #pragma unroll
                for (int mi = 0; mi < 2; mi++)
                    wmma::mma_sync(acc[mi][ni], af[mi], bf, acc[mi][ni]);
            }
        }
        __syncthreads();
    }

    #pragma unroll 1
    for (int p = 0; p < 4; p++) {
        if (wn == p) {
            #pragma unroll
            for (int mi = 0; mi < 2; mi++)
                #pragma unroll
                for (int ni = 0; ni < 4; ni++)
                    wmma::store_matrix_sync(stage + (wm * 32 + mi * 16) * SST + ni * 16,
                                            acc[mi][ni], SST, wmma::mem_row_major);
        }
        __syncthreads();
        #pragma unroll
        for (int j = 0; j < 16; j++) {
            int idx = tid + j * 512;
            int r = idx >> 6, c = idx & 63;
            out[(size_t)(m0 + r) * DF + p * 64 + c] = stage[r * SST + c];
        }
        __syncthreads();
    }
}

// ---------------- launch ----------------
extern "C" void kernel_launch(void* const* d_in, const int* in_sizes, int n_in,
                              void* d_out, int out_size) {
    const float* features = nullptr;
    const float* adj = nullptr;
    const float* W = nullptr;
    for (int i = 0; i < n_in; i++) {
        if (in_sizes[i] == NN * NN) adj = (const float*)d_in[i];
        else if (in_sizes[i] == NN * DF) features = (const float*)d_in[i];
        else if (in_sizes[i] == DF * KCAT) W = (const float*)d_in[i];
    }
    float* out = (float*)d_out;

    cudaFuncSetAttribute(k_main, cudaFuncAttributeMaxDynamicSharedMemorySize, SMEM_MAIN);
    cudaFuncSetAttribute(k_out,  cudaFuncAttributeMaxDynamicSharedMemorySize, SMEM_OUT);

    // k_main stays at launch index 3 (ncu capture slot)
    k_prep<<<dim3(NN / 32, DF / 32), dim3(32, 8)>>>(features);
    k_wconv<<<(DF * KCAT / 2) / 256, 256>>>(W, 0);
    k_wconv<<<(DF * KCAT / 2) / 256, 256>>>(W, DF * KCAT / 2);
    k_main<<<NN / 128, 512, SMEM_MAIN>>>(adj);
    k_out<<<NN / 128, 512, SMEM_OUT>>>(out);
}

// round 9
// speedup vs baseline: 4.5554x; 1.0011x over previous
#include <cuda_runtime.h>
#include <cuda_fp16.h>
#include <mma.h>
#include <cstdint>
#include <cstddef>

using namespace nvcuda;

#define NN   16384
#define DF   256
#define KCAT 512

// ---------------- device-global scratch ----------------
__device__ __half g_ftT[(size_t)DF * NN];    // features^T fp16 [256][16384]
__device__ __half g_cat[(size_t)NN * KCAT];  // [features | neigh] fp16 [16384][512]
__device__ __half g_w[(size_t)DF * KCAT];    // W fp16 [256][512]

// ---------------- k_main smem (FROZEN from R8) ----------------
constexpr int ASTM = 72;
constexpr int A_STG = 128 * ASTM * 2;         // 18432
constexpr int B_STG = 256 * ASTM * 2;         // 36864
constexpr int OFF_BM = 2 * A_STG;             // 36864
constexpr int OFF_SROW = OFF_BM + 3 * B_STG;  // 147456
constexpr int SMEM_MAIN = OFF_SROW + 512;

// ---------------- k_out smem: 4-stage, BK=32 ----------------
constexpr int AST = 40;                        // row stride (halves)
constexpr int AO_STG = 128 * AST * 2;          // 10240 B
constexpr int BO_STG = 256 * AST * 2;          // 20480 B
constexpr int OFF_BO = 4 * AO_STG;             // 40960
constexpr int SST = 68;                        // f32 stage stride (reuse of A region)
constexpr int SMEM_OUT = OFF_BO + 4 * BO_STG + 512;  // 123392

__device__ __forceinline__ uint32_t smem_u32(const void* p) {
    uint32_t a;
    asm("{ .reg .u64 t; cvta.to.shared.u64 t, %1; cvt.u32.u64 %0, t; }" : "=r"(a) : "l"(p));
    return a;
}
__device__ __forceinline__ void cpa16(uint32_t saddr, const void* g) {
    asm volatile("cp.async.cg.shared.global [%0], [%1], 16;" :: "r"(saddr), "l"(g));
}
__device__ __forceinline__ void cpa_commit() { asm volatile("cp.async.commit_group;" ::: "memory"); }
__device__ __forceinline__ void cpa_wait0()  { asm volatile("cp.async.wait_group 0;" ::: "memory"); }
__device__ __forceinline__ void cpa_wait1()  { asm volatile("cp.async.wait_group 1;" ::: "memory"); }
__device__ __forceinline__ void cpa_wait2()  { asm volatile("cp.async.wait_group 2;" ::: "memory"); }

// ---------------- prep ----------------
__global__ void __launch_bounds__(256) k_prep(const float* __restrict__ f) {
    __shared__ float t[32][33];
    int n0 = blockIdx.x * 32, d0 = blockIdx.y * 32;
    int tx = threadIdx.x, ty = threadIdx.y;
    #pragma unroll
    for (int i = ty; i < 32; i += 8) {
        float v = f[(size_t)(n0 + i) * DF + d0 + tx];
        t[i][tx] = v;
        g_cat[(size_t)(n0 + i) * KCAT + d0 + tx] = __float2half(v);
    }
    __syncthreads();
    #pragma unroll
    for (int i = ty; i < 32; i += 8)
        g_ftT[(size_t)(d0 + i) * NN + n0 + tx] = __float2half(t[tx][i]);
}

__global__ void __launch_bounds__(256) k_wconv(const float* __restrict__ W, int base) {
    int i = base + blockIdx.x * 256 + threadIdx.x;
    g_w[i] = __float2half(W[i]);
}

// ================= k_main: FROZEN R8 (512 threads, 16 warps, 32x64 tiles) =================
__global__ void __launch_bounds__(512, 1) k_main(const float* __restrict__ adj) {
    extern __shared__ char sm[];
    __half* Abuf = (__half*)sm;
    __half* Bbuf = (__half*)(sm + OFF_BM);
    float*  srow = (float*)(sm + OFF_SROW);
    __half* hstage = (__half*)sm;

    const int tid = threadIdx.x;
    const int lane = tid & 31;
    const int wid = tid >> 5;
    const int wm = wid >> 2, wn = wid & 3;
    const int m0 = blockIdx.x * 128;
    const uint32_t b_u32 = smem_u32(Bbuf);

    wmma::fragment<wmma::accumulator, 16, 16, 16, __half> acc[2][4];
    #pragma unroll
    for (int mi = 0; mi < 2; mi++)
        #pragma unroll
        for (int ni = 0; ni < 4; ni++)
            wmma::fill_fragment(acc[mi][ni], __float2half(0.0f));

    float rowacc[4] = {0.f, 0.f, 0.f, 0.f};
    float4 va[4];

    auto ldgA = [&](int it) {
        int k0 = it * 64;
        #pragma unroll
        for (int j = 0; j < 4; j++) {
            int idx = tid + j * 512;
            int row = idx >> 4, c4 = idx & 15;
            va[j] = *(const float4*)(adj + (size_t)(m0 + row) * NN + k0 + c4 * 4);
        }
    };
    auto stsA = [&](int buf) {
        __half* At = Abuf + buf * 128 * ASTM;
        #pragma unroll
        for (int j = 0; j < 4; j++) {
            int idx = tid + j * 512;
            int row = idx >> 4, c4 = idx & 15;
            float4 v = va[j];
            rowacc[j] += (v.x + v.y) + (v.z + v.w);
            __half2 h0 = __floats2half2_rn(v.x, v.y);
            __half2 h1 = __floats2half2_rn(v.z, v.w);
            uint2 u;
            u.x = *(uint32_t*)&h0;
            u.y = *(uint32_t*)&h1;
            *(uint2*)(At + row * ASTM + c4 * 4) = u;
        }
    };
    auto cpaB = [&](int buf, int it) {
        int k0 = it * 64;
        uint32_t b0 = b_u32 + buf * B_STG;
        #pragma unroll
        for (int j = 0; j < 4; j++) {
            int idx = tid + j * 512;
            int row = idx >> 3, c16 = idx & 7;
            cpa16(b0 + (row * ASTM + c16 * 8) * 2, g_ftT + (size_t)row * NN + k0 + c16 * 8);
        }
    };

    ldgA(0);
    stsA(0);
    ldgA(1);
    cpaB(0, 0); cpa_commit();
    cpaB(1, 1); cpa_commit();

    constexpr int NK = NN / 64;  // 256
    int bs = 0, bs2 = 2;

    #pragma unroll 1
    for (int it = 0; it < NK; ++it) {
        int cur = it & 1;
        cpa_wait1();
        __syncthreads();

        if (it + 1 < NK) stsA(cur ^ 1);
        if (it + 2 < NK) {
            ldgA(it + 2);
            cpaB(bs2, it + 2);
        }
        cpa_commit();

        const __half* At = Abuf + cur * 128 * ASTM;
        const __half* Bt = Bbuf + bs * 256 * ASTM;
        #pragma unroll
        for (int ks = 0; ks < 4; ++ks) {
            wmma::fragment<wmma::matrix_a, 16, 16, 16, __half, wmma::row_major> af[2];
            #pragma unroll
            for (int mi = 0; mi < 2; mi++)
                wmma::load_matrix_sync(af[mi], At + (wm * 32 + mi * 16) * ASTM + ks * 16, ASTM);
            #pragma unroll
            for (int ni = 0; ni < 4; ni++) {
                wmma::fragment<wmma::matrix_b, 16, 16, 16, __half, wmma::col_major> bf;
                wmma::load_matrix_sync(bf, Bt + (wn * 64 + ni * 16) * ASTM + ks * 16, ASTM);
                #pragma unroll
                for (int mi = 0; mi < 2; mi++)
                    wmma::mma_sync(acc[mi][ni], af[mi], bf, acc[mi][ni]);
            }
        }
        bs = (bs == 2) ? 0 : bs + 1;
        bs2 = (bs2 == 2) ? 0 : bs2 + 1;
    }
    cpa_wait0();

    #pragma unroll
    for (int j = 0; j < 4; j++) {
        float s = rowacc[j];
        s += __shfl_xor_sync(0xFFFFFFFFu, s, 1);
        s += __shfl_xor_sync(0xFFFFFFFFu, s, 2);
        s += __shfl_xor_sync(0xFFFFFFFFu, s, 4);
        s += __shfl_xor_sync(0xFFFFFFFFu, s, 8);
        int row = (tid + j * 512) >> 4;
        if ((lane & 15) == 0) srow[row] = 1.0f / (s + 1.0f);
    }
    __syncthreads();

    #pragma unroll 1
    for (int p = 0; p < 4; p++) {
        if (wn == p) {
            #pragma unroll
            for (int mi = 0; mi < 2; mi++)
                #pragma unroll
                for (int ni = 0; ni < 4; ni++)
                    wmma::store_matrix_sync(hstage + (wm * 32 + mi * 16) * ASTM + ni * 16,
                                            acc[mi][ni], ASTM, wmma::mem_row_major);
        }
        __syncthreads();
        #pragma unroll
        for (int j = 0; j < 16; j++) {
            int idx = tid + j * 512;
            int r = idx >> 6, c = idx & 63;
            float v = __half2float(hstage[r * ASTM + c]) * srow[r];
            g_cat[(size_t)(m0 + r) * KCAT + 256 + p * 64 + c] = __float2half(v);
        }
        __syncthreads();
    }
}

// ================= k_out: 4-stage depth-3 pipeline, BK=32, 512 threads =================
__global__ void __launch_bounds__(512, 1) k_out(float* __restrict__ out) {
    extern __shared__ char sm[];
    __half* Abuf = (__half*)sm;                // [4][128][40]
    __half* Bbuf = (__half*)(sm + OFF_BO);     // [4][256][40]
    float*  stage = (float*)sm;                // epilogue reuse [128][68] f32

    const int tid = threadIdx.x;
    const int wid = tid >> 5;
    const int wm = wid >> 2, wn = wid & 3;     // 4x4 warps, 32x64 tiles
    const int m0 = blockIdx.x * 128;
    const uint32_t a_u32 = smem_u32(Abuf);
    const uint32_t b_u32 = smem_u32(Bbuf);

    wmma::fragment<wmma::accumulator, 16, 16, 16, float> acc[2][4];
    #pragma unroll
    for (int mi = 0; mi < 2; mi++)
        #pragma unroll
        for (int ni = 0; ni < 4; ni++)
            wmma::fill_fragment(acc[mi][ni], 0.0f);

    auto loadTile = [&](int slot, int it) {
        int k0 = it * 32;
        uint32_t a0 = a_u32 + slot * AO_STG;
        uint32_t b0 = b_u32 + slot * BO_STG;
        {   // A: 128 rows x 4 x 16B chunks = 512 loads
            int row = tid >> 2, c8 = tid & 3;
            cpa16(a0 + (row * AST + c8 * 8) * 2, g_cat + (size_t)(m0 + row) * KCAT + k0 + c8 * 8);
        }
        #pragma unroll
        for (int j = 0; j < 2; j++) {  // B: 256 rows x 4 chunks = 1024 loads
            int idx = tid + j * 512;
            int row = idx >> 2, c8 = idx & 3;
            cpa16(b0 + (row * AST + c8 * 8) * 2, g_w + (size_t)row * KCAT + k0 + c8 * 8);
        }
    };

    // prologue: stages 0..2 in flight
    loadTile(0, 0); cpa_commit();
    loadTile(1, 1); cpa_commit();
    loadTile(2, 2); cpa_commit();

    constexpr int NK = KCAT / 32;  // 16
    #pragma unroll 1
    for (int it = 0; it < NK; ++it) {
        int cur = it & 3;
        cpa_wait2();       // tile(it) landed (<=2 younger groups outstanding)
        __syncthreads();   // all warps done reading slot (it-1)%4 == (it+3)%4

        if (it + 3 < NK) { loadTile((it + 3) & 3, it + 3); cpa_commit(); }

        const __half* At = Abuf + cur * 128 * AST;
        const __half* Bt = Bbuf + cur * 256 * AST;
        #pragma unroll
        for (int ks = 0; ks < 2; ++ks) {
            wmma::fragment<wmma::matrix_a, 16, 16, 16, __half, wmma::row_major> af[2];
            #pragma unroll
            for (int mi = 0; mi < 2; mi++)
                wmma::load_matrix_sync(af[mi], At + (wm * 32 + mi * 16) * AST + ks * 16, AST);
            #pragma unroll
            for (int ni = 0; ni < 4; ni++) {
                wmma::fragment<wmma::matrix_b, 16, 16, 16, __half, wmma::col_major> bf;
                wmma::load_matrix_sync(bf, Bt + (wn * 64 + ni * 16) * AST + ks * 16, AST);
                #pragma unroll
                for (int mi = 0; mi < 2; mi++)
                    wmma::mma_sync(acc[mi][ni], af[mi], bf, acc[mi][ni]);
            }
        }
    }
    cpa_wait0();
    __syncthreads();  // safe to overwrite Abuf with f32 stage

    #pragma unroll 1
    for (int p = 0; p < 4; p++) {
        if (wn == p) {
            #pragma unroll
            for (int mi = 0; mi < 2; mi++)
                #pragma unroll
                for (int ni = 0; ni < 4; ni++)
                    wmma::store_matrix_sync(stage + (wm * 32 + mi * 16) * SST + ni * 16,
                                            acc[mi][ni], SST, wmma::mem_row_major);
        }
        __syncthreads();
        #pragma unroll
        for (int j = 0; j < 16; j++) {
            int idx = tid + j * 512;
            int r = idx >> 6, c = idx & 63;
            out[(size_t)(m0 + r) * DF + p * 64 + c] = stage[r * SST + c];
        }
        __syncthreads();
    }
}

// ---------------- launch ----------------
extern "C" void kernel_launch(void* const* d_in, const int* in_sizes, int n_in,
                              void* d_out, int out_size) {
    const float* features = nullptr;
    const float* adj = nullptr;
    const float* W = nullptr;
    for (int i = 0; i < n_in; i++) {
        if (in_sizes[i] == NN * NN) adj = (const float*)d_in[i];
        else if (in_sizes[i] == NN * DF) features = (const float*)d_in[i];
        else if (in_sizes[i] == DF * KCAT) W = (const float*)d_in[i];
    }
    float* out = (float*)d_out;

    cudaFuncSetAttribute(k_main, cudaFuncAttributeMaxDynamicSharedMemorySize, SMEM_MAIN);
    cudaFuncSetAttribute(k_out,  cudaFuncAttributeMaxDynamicSharedMemorySize, SMEM_OUT);

    // k_main stays at launch index 3 (ncu capture slot); k_out at 4
    k_prep<<<dim3(NN / 32, DF / 32), dim3(32, 8)>>>(features);
    k_wconv<<<(DF * KCAT / 2) / 256, 256>>>(W, 0);
    k_wconv<<<(DF * KCAT / 2) / 256, 256>>>(W, DF * KCAT / 2);
    k_main<<<NN / 128, 512, SMEM_MAIN>>>(adj);
    k_out<<<NN / 128, 512, SMEM_OUT>>>(out);
}